// round 8
// baseline (speedup 1.0000x reference)
#include <cuda_runtime.h>
#include <cuda_bf16.h>

// ANFIS fuzzy inference, batch=2M rows x 4 features.
// out = sum_j(w_j * clip(conseq_j)) / max(sum_j w_j, 1e-8),
// w_j = prod of 4 Gaussian memberships.
//
// Structure:
//  - prep kernel computes a' = (1/sigma)*sqrt(0.5*log2 e), b' = -c*a',
//    cq = clip(conseq,0,100) into a __device__ scratch; a 208-byte D2D
//    memcpy moves them into __constant__ memory (graph-capturable).
//  - main kernel reads constants from the constant bank (LDCU/uniform-reg
//    path on sm_100a): zero GPR cost, zero L1/shared traffic, no smem,
//    no __syncthreads.
//  - mu_i = ex2((-d)*d) (negation folded into FMUL source modifier).
//  - pair-product CSE: P[9] = mu[0..2] x mu[3..5], Q[6] = mu[6..8] x mu[9..10].
//  - group factorization over the 6 shared Q factors; split accumulators;
//    CSE'd unweighted group sums.
//  - 4 rows/thread, 256-thread blocks.

namespace {
// Rules grouped by q = (ante2-6)*2 + (ante3-9); p = ante0*3 + (ante1-3).
// Verified against RULE_ANTECEDENTS.
__device__ constexpr int GRP_OFF[7] = {0, 7, 11, 16, 21, 26, 30};
__device__ constexpr int GRP_P[30]  = {0,3,1,2,8,5,7,  8,7,5,4,  0,4,3,6,5,
                                       0,1,3,2,8,  0,1,3,2,7,  0,1,3,4};
__device__ constexpr int GRP_CQ[30] = {9,13,15,19,23,27,28,  22,24,25,29,
                                       2,11,17,18,20,  4,10,12,14,26,
                                       0,3,6,7,21,  1,5,8,16};
__device__ constexpr int DM[11] = {0,0,0,1,1,1,2,2,2,3,3};
}

// Preprocessed constants: [0..10]=a', [11..21]=b', [22..51]=cq.
__device__   float g_scratch[52];
__constant__ float g_cst[52];

__device__ __forceinline__ float ex2(float t) {
    float r; asm("ex2.approx.ftz.f32 %0, %1;" : "=f"(r) : "f"(t)); return r;
}

__global__ void prep_kernel(const float* __restrict__ c,
                            const float* __restrict__ log_s,
                            const float* __restrict__ conseq)
{
    const int t = threadIdx.x;
    if (t < 11) {
        const float KS = 0.8493218002880191f;  // sqrt(0.5 * log2(e))
        float ci  = c[t];
        float sg  = fmaxf(__expf(log_s[t]), 0.001f);
        float ap  = KS / sg;
        g_scratch[t]      = ap;
        g_scratch[11 + t] = -ci * ap;
    }
    if (t < 30) {
        g_scratch[22 + t] = fminf(fmaxf(conseq[t], 0.0f), 100.0f);
    }
}

constexpr int THREADS = 256;
constexpr int ROWS_PER_THREAD = 4;
constexpr int TILE = THREADS * ROWS_PER_THREAD;   // 1024 rows/block

__device__ __forceinline__ float anfis_row(const float4 xv)
{
    const float xd[4] = {xv.x, xv.y, xv.z, xv.w};

    // 11 memberships: FFMA + FMUL(neg-src) + MUFU each; a'/b' from cbank.
    float mu[11];
    #pragma unroll
    for (int i = 0; i < 11; i++) {
        float d = fmaf(xd[DM[i]], g_cst[i], g_cst[11 + i]);
        mu[i] = ex2(-d * d);
    }

    // Pair products.
    float Pv[9], Qv[6];
    #pragma unroll
    for (int i = 0; i < 3; i++)
        #pragma unroll
        for (int j = 0; j < 3; j++)
            Pv[i * 3 + j] = mu[i] * mu[3 + j];
    #pragma unroll
    for (int i = 0; i < 3; i++)
        #pragma unroll
        for (int j = 0; j < 2; j++)
            Qv[i * 2 + j] = mu[6 + i] * mu[9 + j];

    // Weighted group inner sums (cq from cbank; 6 MUL + 24 FMA).
    float s1[6];
    #pragma unroll
    for (int g = 0; g < 6; g++) {
        const int m0 = GRP_OFF[g], m1 = GRP_OFF[g + 1];
        float s = Pv[GRP_P[m0]] * g_cst[22 + GRP_CQ[m0]];
        #pragma unroll
        for (int m = m0 + 1; m < m1; m++)
            s = fmaf(Pv[GRP_P[m]], g_cst[22 + GRP_CQ[m]], s);
        s1[g] = s;
    }

    // Unweighted group sums with CSE (16 ADDs).
    float u = (Pv[0] + Pv[1]) + Pv[3];   // {0,1,3}
    float v = u + Pv[2];                 // {0,1,2,3}
    float s0_0 = v + ((Pv[8] + Pv[5]) + Pv[7]);
    float s0_1 = (Pv[8] + Pv[7]) + (Pv[5] + Pv[4]);
    float s0_2 = ((Pv[0] + Pv[4]) + (Pv[3] + Pv[6])) + Pv[5];
    float s0_3 = v + Pv[8];
    float s0_4 = v + Pv[7];
    float s0_5 = u + Pv[4];

    // Split accumulators: two independent 3-op chains each.
    float accA = Qv[0] * s1[0];
    float accB = Qv[1] * s1[1];
    accA = fmaf(Qv[2], s1[2], accA);
    accB = fmaf(Qv[3], s1[3], accB);
    accA = fmaf(Qv[4], s1[4], accA);
    accB = fmaf(Qv[5], s1[5], accB);

    float wsA = Qv[0] * s0_0;
    float wsB = Qv[1] * s0_1;
    wsA = fmaf(Qv[2], s0_2, wsA);
    wsB = fmaf(Qv[3], s0_3, wsB);
    wsA = fmaf(Qv[4], s0_4, wsA);
    wsB = fmaf(Qv[5], s0_5, wsB);

    return __fdividef(accA + accB, fmaxf(wsA + wsB, 1e-8f));
}

__global__ void __launch_bounds__(THREADS)
anfis_kernel(const float4* __restrict__ x,
             float* __restrict__ out,
             int n)
{
    const int base = blockIdx.x * TILE + threadIdx.x;

    if (blockIdx.x * TILE + TILE <= n) {
        // Full tile: 4 unconditional coalesced LDG.128 (MLP=4).
        float4 xv[ROWS_PER_THREAD];
        #pragma unroll
        for (int k = 0; k < ROWS_PER_THREAD; k++)
            xv[k] = __ldg(x + base + k * THREADS);

        float res[ROWS_PER_THREAD];
        #pragma unroll
        for (int k = 0; k < ROWS_PER_THREAD; k++)
            res[k] = anfis_row(xv[k]);

        #pragma unroll
        for (int k = 0; k < ROWS_PER_THREAD; k++)
            out[base + k * THREADS] = res[k];
    } else {
        // Tail: predicated.
        #pragma unroll
        for (int k = 0; k < ROWS_PER_THREAD; k++) {
            int r = base + k * THREADS;
            if (r < n) {
                float4 xv = __ldg(x + r);
                out[r] = anfis_row(xv);
            }
        }
    }
}

extern "C" void kernel_launch(void* const* d_in, const int* in_sizes, int n_in,
                              void* d_out, int out_size)
{
    const float* x      = (const float*)d_in[0];
    const float* c      = (const float*)d_in[1];
    const float* log_s  = (const float*)d_in[2];
    const float* conseq = (const float*)d_in[3];
    float* out          = (float*)d_out;

    int n = in_sizes[0] / 4;   // rows
    int blocks = (n + TILE - 1) / TILE;

    // 1) Preprocess constants into __device__ scratch.
    prep_kernel<<<1, 32>>>(c, log_s, conseq);

    // 2) Move scratch -> __constant__ bank (208 B, D2D async memcpy node).
    void* scratch_ptr = nullptr;
    cudaGetSymbolAddress(&scratch_ptr, g_scratch);
    cudaMemcpyToSymbolAsync(g_cst, scratch_ptr, 52 * sizeof(float), 0,
                            cudaMemcpyDeviceToDevice, 0);

    // 3) Main kernel: constants served from the constant bank.
    anfis_kernel<<<blocks, THREADS>>>((const float4*)x, out, n);
}

// round 9
// speedup vs baseline: 1.0907x; 1.0907x over previous
#include <cuda_runtime.h>
#include <cuda_bf16.h>

// ANFIS fuzzy inference, batch=2M rows x 4 features.
// out = sum_j(w_j * clip(conseq_j)) / max(sum_j w_j, 1e-8),
// w_j = prod of 4 Gaussian memberships.
//
// Two graph nodes:
//  1) prep kernel computes a' = (1/sigma)*sqrt(0.5*log2 e), b' = -c*a',
//     cq = clip(conseq,0,100) and stores them DIRECTLY into the __constant__
//     symbol's backing store (device address via cudaGetSymbolAddress).
//     Constant caches are invalidated at launch boundaries, so the main
//     kernel's cbank reads see the new values (same visibility path a
//     D2D cudaMemcpyToSymbol uses).
//  2) main kernel: constants served from the constant bank (uniform path,
//     zero GPR cost, zero L1/shared traffic), no smem, no __syncthreads.
//
// Row math:
//  - mu_i = ex2((-d)*d), d = x*a'+b' (negation folded into FMUL operand).
//  - pair-product CSE: P[9] = mu[0..2] x mu[3..5], Q[6] = mu[6..8] x mu[9..10].
//  - group factorization over the 6 shared Q factors; split accumulators;
//    CSE'd unweighted group sums.
//  - 2 rows/thread (smaller live set -> <=40 regs -> 6 CTAs/SM), 256 threads.

namespace {
// Rules grouped by q = (ante2-6)*2 + (ante3-9); p = ante0*3 + (ante1-3).
// Verified against RULE_ANTECEDENTS.
__device__ constexpr int GRP_OFF[7] = {0, 7, 11, 16, 21, 26, 30};
__device__ constexpr int GRP_P[30]  = {0,3,1,2,8,5,7,  8,7,5,4,  0,4,3,6,5,
                                       0,1,3,2,8,  0,1,3,2,7,  0,1,3,4};
__device__ constexpr int GRP_CQ[30] = {9,13,15,19,23,27,28,  22,24,25,29,
                                       2,11,17,18,20,  4,10,12,14,26,
                                       0,3,6,7,21,  1,5,8,16};
__device__ constexpr int DM[11] = {0,0,0,1,1,1,2,2,2,3,3};
}

// Preprocessed constants: [0..10]=a', [11..21]=b', [22..51]=cq.
__constant__ float g_cst[52];

__device__ __forceinline__ float ex2(float t) {
    float r; asm("ex2.approx.ftz.f32 %0, %1;" : "=f"(r) : "f"(t)); return r;
}

// Writes the __constant__ backing store directly (cst_backing = device
// address of g_cst). Visible to subsequent launches via L2.
__global__ void prep_kernel(const float* __restrict__ c,
                            const float* __restrict__ log_s,
                            const float* __restrict__ conseq,
                            float* __restrict__ cst_backing)
{
    const int t = threadIdx.x;
    if (t < 11) {
        const float KS = 0.8493218002880191f;  // sqrt(0.5 * log2(e))
        float ci  = c[t];
        float sg  = fmaxf(__expf(log_s[t]), 0.001f);
        float ap  = KS / sg;
        cst_backing[t]      = ap;
        cst_backing[11 + t] = -ci * ap;
    }
    if (t < 30) {
        cst_backing[22 + t] = fminf(fmaxf(conseq[t], 0.0f), 100.0f);
    }
    __threadfence();   // order stores to L2 before kernel end
}

constexpr int THREADS = 256;
constexpr int ROWS_PER_THREAD = 2;
constexpr int TILE = THREADS * ROWS_PER_THREAD;   // 512 rows/block

__device__ __forceinline__ float anfis_row(const float4 xv)
{
    const float xd[4] = {xv.x, xv.y, xv.z, xv.w};

    // 11 memberships: FFMA + FMUL(neg-src) + MUFU each; a'/b' from cbank.
    float mu[11];
    #pragma unroll
    for (int i = 0; i < 11; i++) {
        float d = fmaf(xd[DM[i]], g_cst[i], g_cst[11 + i]);
        mu[i] = ex2(-d * d);
    }

    // Pair products.
    float Pv[9], Qv[6];
    #pragma unroll
    for (int i = 0; i < 3; i++)
        #pragma unroll
        for (int j = 0; j < 3; j++)
            Pv[i * 3 + j] = mu[i] * mu[3 + j];
    #pragma unroll
    for (int i = 0; i < 3; i++)
        #pragma unroll
        for (int j = 0; j < 2; j++)
            Qv[i * 2 + j] = mu[6 + i] * mu[9 + j];

    // Weighted group inner sums (cq from cbank; 6 MUL + 24 FMA).
    float s1[6];
    #pragma unroll
    for (int g = 0; g < 6; g++) {
        const int m0 = GRP_OFF[g], m1 = GRP_OFF[g + 1];
        float s = Pv[GRP_P[m0]] * g_cst[22 + GRP_CQ[m0]];
        #pragma unroll
        for (int m = m0 + 1; m < m1; m++)
            s = fmaf(Pv[GRP_P[m]], g_cst[22 + GRP_CQ[m]], s);
        s1[g] = s;
    }

    // Unweighted group sums with CSE (16 ADDs).
    float u = (Pv[0] + Pv[1]) + Pv[3];   // {0,1,3}
    float v = u + Pv[2];                 // {0,1,2,3}
    float s0_0 = v + ((Pv[8] + Pv[5]) + Pv[7]);
    float s0_1 = (Pv[8] + Pv[7]) + (Pv[5] + Pv[4]);
    float s0_2 = ((Pv[0] + Pv[4]) + (Pv[3] + Pv[6])) + Pv[5];
    float s0_3 = v + Pv[8];
    float s0_4 = v + Pv[7];
    float s0_5 = u + Pv[4];

    // Split accumulators: two independent 3-op chains each.
    float accA = Qv[0] * s1[0];
    float accB = Qv[1] * s1[1];
    accA = fmaf(Qv[2], s1[2], accA);
    accB = fmaf(Qv[3], s1[3], accB);
    accA = fmaf(Qv[4], s1[4], accA);
    accB = fmaf(Qv[5], s1[5], accB);

    float wsA = Qv[0] * s0_0;
    float wsB = Qv[1] * s0_1;
    wsA = fmaf(Qv[2], s0_2, wsA);
    wsB = fmaf(Qv[3], s0_3, wsB);
    wsA = fmaf(Qv[4], s0_4, wsA);
    wsB = fmaf(Qv[5], s0_5, wsB);

    return __fdividef(accA + accB, fmaxf(wsA + wsB, 1e-8f));
}

__global__ void __launch_bounds__(THREADS)
anfis_kernel(const float4* __restrict__ x,
             float* __restrict__ out,
             int n)
{
    const int base = blockIdx.x * TILE + threadIdx.x;

    if (blockIdx.x * TILE + TILE <= n) {
        // Full tile: 2 unconditional coalesced LDG.128.
        float4 xv0 = __ldg(x + base);
        float4 xv1 = __ldg(x + base + THREADS);

        float r0 = anfis_row(xv0);
        float r1 = anfis_row(xv1);

        out[base]           = r0;
        out[base + THREADS] = r1;
    } else {
        // Tail: predicated.
        #pragma unroll
        for (int k = 0; k < ROWS_PER_THREAD; k++) {
            int r = base + k * THREADS;
            if (r < n) {
                float4 xv = __ldg(x + r);
                out[r] = anfis_row(xv);
            }
        }
    }
}

extern "C" void kernel_launch(void* const* d_in, const int* in_sizes, int n_in,
                              void* d_out, int out_size)
{
    const float* x      = (const float*)d_in[0];
    const float* c      = (const float*)d_in[1];
    const float* log_s  = (const float*)d_in[2];
    const float* conseq = (const float*)d_in[3];
    float* out          = (float*)d_out;

    int n = in_sizes[0] / 4;   // rows
    int blocks = (n + TILE - 1) / TILE;

    // Device address of the __constant__ symbol (host API, capture-legal,
    // no allocation). Prep kernel stores the preprocessed constants there.
    void* cst_ptr = nullptr;
    cudaGetSymbolAddress(&cst_ptr, g_cst);

    prep_kernel<<<1, 32>>>(c, log_s, conseq, (float*)cst_ptr);
    anfis_kernel<<<blocks, THREADS>>>((const float4*)x, out, n);
}

// round 10
// speedup vs baseline: 1.1226x; 1.0292x over previous
#include <cuda_runtime.h>
#include <cuda_bf16.h>

// ANFIS fuzzy inference, batch=2M rows x 4 features.
// out = sum_j(w_j * clip(conseq_j)) / max(sum_j w_j, 1e-8),
// w_j = prod of 4 Gaussian memberships.
//
// Two graph nodes with PDL overlap:
//  1) prep kernel computes a' = (1/sigma)*sqrt(0.5*log2 e), b' = -c*a',
//     cq = clip(conseq,0,100) directly into the __constant__ backing store,
//     then triggers programmatic launch completion.
//  2) main kernel is launched with ProgrammaticStreamSerialization: its grid
//     launches while prep is in flight; each thread issues its x-row LDGs
//     (independent of prep), then cudaGridDependencySynchronize() before the
//     first g_cst read. Constants served from the constant bank (uniform
//     path: zero GPR cost, zero L1/shared traffic).
//
// Row math (unchanged from R9 body, 14.2us standalone):
//  - mu_i = ex2((-d)*d), d = x*a'+b' (negation folded into FMUL operand).
//  - pair-product CSE: P[9] = mu[0..2] x mu[3..5], Q[6] = mu[6..8] x mu[9..10].
//  - group factorization over the 6 shared Q factors; split accumulators;
//    CSE'd unweighted group sums.
//  - 2 rows/thread, 256 threads, regs ~32 -> occ ~81%.

namespace {
// Rules grouped by q = (ante2-6)*2 + (ante3-9); p = ante0*3 + (ante1-3).
// Verified against RULE_ANTECEDENTS.
__device__ constexpr int GRP_OFF[7] = {0, 7, 11, 16, 21, 26, 30};
__device__ constexpr int GRP_P[30]  = {0,3,1,2,8,5,7,  8,7,5,4,  0,4,3,6,5,
                                       0,1,3,2,8,  0,1,3,2,7,  0,1,3,4};
__device__ constexpr int GRP_CQ[30] = {9,13,15,19,23,27,28,  22,24,25,29,
                                       2,11,17,18,20,  4,10,12,14,26,
                                       0,3,6,7,21,  1,5,8,16};
__device__ constexpr int DM[11] = {0,0,0,1,1,1,2,2,2,3,3};
}

// Preprocessed constants: [0..10]=a', [11..21]=b', [22..51]=cq.
__constant__ float g_cst[52];

__device__ __forceinline__ float ex2(float t) {
    float r; asm("ex2.approx.ftz.f32 %0, %1;" : "=f"(r) : "f"(t)); return r;
}

// Writes the __constant__ backing store directly, then signals that the
// dependent grid may launch.
__global__ void prep_kernel(const float* __restrict__ c,
                            const float* __restrict__ log_s,
                            const float* __restrict__ conseq,
                            float* __restrict__ cst_backing)
{
    const int t = threadIdx.x;
    if (t < 11) {
        const float KS = 0.8493218002880191f;  // sqrt(0.5 * log2(e))
        float ci  = c[t];
        float sg  = fmaxf(__expf(log_s[t]), 0.001f);
        float ap  = KS / sg;
        cst_backing[t]      = ap;
        cst_backing[11 + t] = -ci * ap;
    }
    if (t < 30) {
        cst_backing[22 + t] = fminf(fmaxf(conseq[t], 0.0f), 100.0f);
    }
    __threadfence();   // order stores to L2 before the trigger
#if __CUDA_ARCH__ >= 900
    cudaTriggerProgrammaticLaunchCompletion();
#endif
}

constexpr int THREADS = 256;
constexpr int ROWS_PER_THREAD = 2;
constexpr int TILE = THREADS * ROWS_PER_THREAD;   // 512 rows/block

__device__ __forceinline__ float anfis_row(const float4 xv)
{
    const float xd[4] = {xv.x, xv.y, xv.z, xv.w};

    // 11 memberships: FFMA + FMUL(neg-src) + MUFU each; a'/b' from cbank.
    float mu[11];
    #pragma unroll
    for (int i = 0; i < 11; i++) {
        float d = fmaf(xd[DM[i]], g_cst[i], g_cst[11 + i]);
        mu[i] = ex2(-d * d);
    }

    // Pair products.
    float Pv[9], Qv[6];
    #pragma unroll
    for (int i = 0; i < 3; i++)
        #pragma unroll
        for (int j = 0; j < 3; j++)
            Pv[i * 3 + j] = mu[i] * mu[3 + j];
    #pragma unroll
    for (int i = 0; i < 3; i++)
        #pragma unroll
        for (int j = 0; j < 2; j++)
            Qv[i * 2 + j] = mu[6 + i] * mu[9 + j];

    // Weighted group inner sums (cq from cbank; 6 MUL + 24 FMA).
    float s1[6];
    #pragma unroll
    for (int g = 0; g < 6; g++) {
        const int m0 = GRP_OFF[g], m1 = GRP_OFF[g + 1];
        float s = Pv[GRP_P[m0]] * g_cst[22 + GRP_CQ[m0]];
        #pragma unroll
        for (int m = m0 + 1; m < m1; m++)
            s = fmaf(Pv[GRP_P[m]], g_cst[22 + GRP_CQ[m]], s);
        s1[g] = s;
    }

    // Unweighted group sums with CSE (16 ADDs).
    float u = (Pv[0] + Pv[1]) + Pv[3];   // {0,1,3}
    float v = u + Pv[2];                 // {0,1,2,3}
    float s0_0 = v + ((Pv[8] + Pv[5]) + Pv[7]);
    float s0_1 = (Pv[8] + Pv[7]) + (Pv[5] + Pv[4]);
    float s0_2 = ((Pv[0] + Pv[4]) + (Pv[3] + Pv[6])) + Pv[5];
    float s0_3 = v + Pv[8];
    float s0_4 = v + Pv[7];
    float s0_5 = u + Pv[4];

    // Split accumulators: two independent 3-op chains each.
    float accA = Qv[0] * s1[0];
    float accB = Qv[1] * s1[1];
    accA = fmaf(Qv[2], s1[2], accA);
    accB = fmaf(Qv[3], s1[3], accB);
    accA = fmaf(Qv[4], s1[4], accA);
    accB = fmaf(Qv[5], s1[5], accB);

    float wsA = Qv[0] * s0_0;
    float wsB = Qv[1] * s0_1;
    wsA = fmaf(Qv[2], s0_2, wsA);
    wsB = fmaf(Qv[3], s0_3, wsB);
    wsA = fmaf(Qv[4], s0_4, wsA);
    wsB = fmaf(Qv[5], s0_5, wsB);

    return __fdividef(accA + accB, fmaxf(wsA + wsB, 1e-8f));
}

__global__ void __launch_bounds__(THREADS)
anfis_kernel(const float4* __restrict__ x,
             float* __restrict__ out,
             int n)
{
    const int base = blockIdx.x * TILE + threadIdx.x;
    const bool full = (blockIdx.x * TILE + TILE <= n);

    if (full) {
        // Issue the x loads BEFORE the dependency sync — they don't depend
        // on prep, so their latency hides under the wait.
        float4 xv0 = __ldg(x + base);
        float4 xv1 = __ldg(x + base + THREADS);

#if __CUDA_ARCH__ >= 900
        cudaGridDependencySynchronize();
#endif

        float r0 = anfis_row(xv0);
        float r1 = anfis_row(xv1);

        out[base]           = r0;
        out[base + THREADS] = r1;
    } else {
#if __CUDA_ARCH__ >= 900
        cudaGridDependencySynchronize();
#endif
        #pragma unroll
        for (int k = 0; k < ROWS_PER_THREAD; k++) {
            int r = base + k * THREADS;
            if (r < n) {
                float4 xv = __ldg(x + r);
                out[r] = anfis_row(xv);
            }
        }
    }
}

extern "C" void kernel_launch(void* const* d_in, const int* in_sizes, int n_in,
                              void* d_out, int out_size)
{
    const float* x      = (const float*)d_in[0];
    const float* c      = (const float*)d_in[1];
    const float* log_s  = (const float*)d_in[2];
    const float* conseq = (const float*)d_in[3];
    float* out          = (float*)d_out;

    int n = in_sizes[0] / 4;   // rows
    int blocks = (n + TILE - 1) / TILE;

    // Device address of the __constant__ symbol (host API, capture-legal,
    // no allocation).
    void* cst_ptr = nullptr;
    cudaGetSymbolAddress(&cst_ptr, g_cst);

    // Node 1: prep (triggers programmatic launch completion early).
    prep_kernel<<<1, 32>>>(c, log_s, conseq, (float*)cst_ptr);

    // Node 2: main kernel with programmatic dependent launch — its grid
    // launches while prep is in flight; griddepsync inside orders the
    // constant reads.
    cudaLaunchConfig_t cfg = {};
    cfg.gridDim  = dim3((unsigned)blocks, 1, 1);
    cfg.blockDim = dim3(THREADS, 1, 1);
    cfg.dynamicSmemBytes = 0;
    cfg.stream = 0;
    cudaLaunchAttribute attrs[1];
    attrs[0].id = cudaLaunchAttributeProgrammaticStreamSerialization;
    attrs[0].val.programmaticStreamSerializationAllowed = 1;
    cfg.attrs = attrs;
    cfg.numAttrs = 1;

    cudaError_t err = cudaLaunchKernelEx(&cfg, anfis_kernel,
                                         (const float4*)x, out, n);
    if (err != cudaSuccess) {
        // Fallback: plain serialized launch (still correct).
        anfis_kernel<<<blocks, THREADS>>>((const float4*)x, out, n);
    }
}